// round 4
// baseline (speedup 1.0000x reference)
#include <cuda_runtime.h>
#include <cstdint>

// ----------------------------------------------------------------------------
// LinearMultiHeadAttention: out = ((x@Wq^T) @ (K^T V per head) * scale) @ Wo^T
// Plan:
//   1) round x, Wq|Wk|Wv (concat), Wo to tf32 (cvt.rna) into scratch
//   2) qkv = x_t @ Wcat_t^T          (tf32 mma GEMM, M=16384 N=3072 K=1024)
//   3) kv[b,h] = K^T V  (fp32, split-S partials + deterministic reduce, *scale)
//   4) attn = q @ kv                  (fp32 FFMA, smem-staged; rounded to tf32)
//   5) out = attn_t @ Wo_t^T          (tf32 mma GEMM, M=16384 N=1024 K=1024)
// ----------------------------------------------------------------------------

static constexpr int BATCH  = 4;
static constexpr int SEQ    = 4096;
static constexpr int DMODEL = 1024;
static constexpr int HEADS  = 16;
static constexpr int DKH    = 64;
static constexpr int NTOK   = BATCH * SEQ;   // 16384
static constexpr int QKVN   = 3 * DMODEL;    // 3072
static constexpr int NSPLIT = 8;
static constexpr int SCHUNK = SEQ / NSPLIT;  // 512

// Scratch (allocation-free rule: __device__ globals)
__device__ float g_xt[NTOK * DMODEL];                         // 64 MB
__device__ float g_wqkv[QKVN * DMODEL];                       // 12 MB
__device__ float g_wo[DMODEL * DMODEL];                       // 4 MB
__device__ float g_qkv[(size_t)NTOK * QKVN];                  // 192 MB
__device__ float g_kvp[NSPLIT * BATCH * HEADS * DKH * DKH];   // 8 MB
__device__ float g_kv[BATCH * HEADS * DKH * DKH];             // 1 MB
__device__ float g_attn[NTOK * DMODEL];                       // 64 MB

__device__ __forceinline__ float tf32_rna(float x) {
    uint32_t u;
    asm("cvt.rna.tf32.f32 %0, %1;" : "=r"(u) : "f"(x));
    return __uint_as_float(u);
}

// ---------------------------------------------------------------- rounding --
__global__ void round_tf32_kernel(const float* __restrict__ s,
                                  float* __restrict__ d, int n4) {
    int i = blockIdx.x * blockDim.x + threadIdx.x;
    int stride = gridDim.x * blockDim.x;
    for (; i < n4; i += stride) {
        float4 v = ((const float4*)s)[i];
        v.x = tf32_rna(v.x); v.y = tf32_rna(v.y);
        v.z = tf32_rna(v.z); v.w = tf32_rna(v.w);
        ((float4*)d)[i] = v;
    }
}

// ---------------------------------------------------------------- tf32 GEMM --
// C[M,N] = A[M,K] @ B[N,K]^T ; A,B row-major, pre-rounded to tf32 bit patterns.
// CTA tile 128x128, K-tile 16, 8 warps (2x4), warp tile 64x32.
// cp.async double-buffered smem (2 stages x (A+B) x 128x16, stride-20 pad).

__device__ __forceinline__ void cp16(float* smem_dst, const float* gmem_src) {
    uint32_t s = (uint32_t)__cvta_generic_to_shared(smem_dst);
    asm volatile("cp.async.cg.shared.global [%0], [%1], 16;"
                 :: "r"(s), "l"(gmem_src) : "memory");
}

static constexpr int SAS     = 20;         // padded row stride (words)
static constexpr int TILE_F  = 128 * SAS;  // 2560 floats per operand tile
static constexpr int STAGE_F = 2 * TILE_F; // A+B per stage

__global__ __launch_bounds__(256, 2)
void gemm_tf32(const float* __restrict__ A, const float* __restrict__ Bm,
               float* __restrict__ C, int K, int ldc) {
    __shared__ float sm[2 * STAGE_F];  // 40960 B

    const int tid  = threadIdx.x;
    const int lane = tid & 31;
    const int warp = tid >> 5;
    const int wm = (warp >> 2) * 64;
    const int wn = (warp & 3) * 32;
    const int m0 = blockIdx.y * 128;
    const int n0 = blockIdx.x * 128;

    const float* Ab = A + (size_t)m0 * K;
    const float* Bb = Bm + (size_t)n0 * K;

    const int lr = tid >> 2;        // 0..63
    const int lc = (tid & 3) * 4;   // 0,4,8,12
    const int nkt = K / 16;

    auto prefetch = [&](int kt, int stage) {
        float* As = sm + stage * STAGE_F;
        float* Bs = As + TILE_F;
        const float* ap = Ab + (size_t)lr * K + kt * 16 + lc;
        const float* bp = Bb + (size_t)lr * K + kt * 16 + lc;
        cp16(As + lr * SAS + lc,        ap);
        cp16(As + (lr + 64) * SAS + lc, ap + (size_t)64 * K);
        cp16(Bs + lr * SAS + lc,        bp);
        cp16(Bs + (lr + 64) * SAS + lc, bp + (size_t)64 * K);
        asm volatile("cp.async.commit_group;" ::: "memory");
    };

    prefetch(0, 0);
    prefetch(1, 1);

    float c[4][4][4];
    #pragma unroll
    for (int i = 0; i < 4; i++)
        #pragma unroll
        for (int j = 0; j < 4; j++)
            #pragma unroll
            for (int k = 0; k < 4; k++) c[i][j][k] = 0.f;

    const int arow = wm + (lane >> 2);
    const int brow = wn + (lane >> 2);
    const int kc   = lane & 3;

    for (int kt = 0; kt < nkt; kt++) {
        if (kt + 1 < nkt) asm volatile("cp.async.wait_group 1;" ::: "memory");
        else              asm volatile("cp.async.wait_group 0;" ::: "memory");
        __syncthreads();

        const float* As = sm + (kt & 1) * STAGE_F;
        const float* Bs = As + TILE_F;

        #pragma unroll
        for (int ks = 0; ks < 2; ks++) {
            uint32_t a[4][4], b[4][2];
            #pragma unroll
            for (int fm = 0; fm < 4; fm++) {
                const float* p = As + (arow + fm * 16) * SAS + ks * 8 + kc;
                a[fm][0] = __float_as_uint(p[0]);
                a[fm][1] = __float_as_uint(p[8 * SAS]);
                a[fm][2] = __float_as_uint(p[4]);
                a[fm][3] = __float_as_uint(p[8 * SAS + 4]);
            }
            #pragma unroll
            for (int fn = 0; fn < 4; fn++) {
                const float* p = Bs + (brow + fn * 8) * SAS + ks * 8 + kc;
                b[fn][0] = __float_as_uint(p[0]);
                b[fn][1] = __float_as_uint(p[4]);
            }
            #pragma unroll
            for (int fm = 0; fm < 4; fm++)
                #pragma unroll
                for (int fn = 0; fn < 4; fn++)
                    asm volatile(
                        "mma.sync.aligned.m16n8k8.row.col.f32.tf32.tf32.f32 "
                        "{%0,%1,%2,%3},{%4,%5,%6,%7},{%8,%9},{%0,%1,%2,%3};"
                        : "+f"(c[fm][fn][0]), "+f"(c[fm][fn][1]),
                          "+f"(c[fm][fn][2]), "+f"(c[fm][fn][3])
                        : "r"(a[fm][0]), "r"(a[fm][1]),
                          "r"(a[fm][2]), "r"(a[fm][3]),
                          "r"(b[fn][0]), "r"(b[fn][1]));
        }
        __syncthreads();
        if (kt + 2 < nkt) prefetch(kt + 2, kt & 1);
    }

    #pragma unroll
    for (int fm = 0; fm < 4; fm++) {
        int r = m0 + wm + fm * 16 + (lane >> 2);
        #pragma unroll
        for (int fn = 0; fn < 4; fn++) {
            int cc = n0 + wn + fn * 8 + (lane & 3) * 2;
            *(float2*)(C + (size_t)r * ldc + cc) =
                make_float2(c[fm][fn][0], c[fm][fn][1]);
            *(float2*)(C + (size_t)(r + 8) * ldc + cc) =
                make_float2(c[fm][fn][2], c[fm][fn][3]);
        }
    }
}

// ------------------------------------------------------------- kv partials --
// kv_partial[sp,b,h,d,e] = sum_{s in chunk} k[b,s,h,d] * v[b,s,h,e]  (fp32)
__global__ void kv_partial_kernel(const float* __restrict__ qkv,
                                  float* __restrict__ kvp) {
    const int sp = blockIdx.x, h = blockIdx.y, b = blockIdx.z;
    const int tid = threadIdx.x;
    __shared__ float ks[16][64];
    __shared__ float vs[16][64];

    const int td = (tid >> 4) * 4;   // d base, 0..60
    const int te = (tid & 15) * 4;   // e base, 0..60
    const int ss = tid >> 4;         // 0..15
    const int dd = (tid & 15) * 4;

    float acc[4][4];
    #pragma unroll
    for (int i = 0; i < 4; i++)
        #pragma unroll
        for (int j = 0; j < 4; j++) acc[i][j] = 0.f;

    const int t0 = b * SEQ + sp * SCHUNK;
    for (int s = 0; s < SCHUNK; s += 16) {
        const float* base = qkv + (size_t)(t0 + s + ss) * QKVN + h * DKH;
        *(float4*)&ks[ss][dd] = *(const float4*)(base + DMODEL + dd);
        *(float4*)&vs[ss][dd] = *(const float4*)(base + 2 * DMODEL + dd);
        __syncthreads();
        #pragma unroll
        for (int j = 0; j < 16; j++) {
            float4 kk = *(const float4*)&ks[j][td];
            float4 vv = *(const float4*)&vs[j][te];
            float ka[4] = {kk.x, kk.y, kk.z, kk.w};
            #pragma unroll
            for (int i = 0; i < 4; i++) {
                acc[i][0] += ka[i] * vv.x;
                acc[i][1] += ka[i] * vv.y;
                acc[i][2] += ka[i] * vv.z;
                acc[i][3] += ka[i] * vv.w;
            }
        }
        __syncthreads();
    }

    float* o = kvp + (size_t)(((sp * BATCH + b) * HEADS + h) * DKH) * DKH;
    #pragma unroll
    for (int i = 0; i < 4; i++)
        *(float4*)(o + (td + i) * DKH + te) =
            make_float4(acc[i][0], acc[i][1], acc[i][2], acc[i][3]);
}

// kv[b,h,d,e] = scale * sum_sp kvp[sp,b,h,d,e]   (deterministic reduce)
__global__ void kv_reduce_kernel(const float* __restrict__ kvp,
                                 float* __restrict__ kv) {
    int idx = blockIdx.x * blockDim.x + threadIdx.x;
    float s = 0.f;
    #pragma unroll
    for (int sp = 0; sp < NSPLIT; sp++)
        s += kvp[(size_t)sp * (BATCH * HEADS * DKH * DKH) + idx];
    kv[idx] = s * 0.125f;   // 1/sqrt(64)
}

// --------------------------------------------------------------------- attn --
// attn[t, h*64+e] = tf32_round( sum_d q[t,h,d] * kv[b,h,d,e] )
__global__ void attn_kernel(const float* __restrict__ qkv,
                            const float* __restrict__ kv,
                            float* __restrict__ attn) {
    const int st = blockIdx.x, h = blockIdx.y, b = blockIdx.z;
    const int tid = threadIdx.x;
    __shared__ float kvs[DKH][DKH];   // 16 KB
    __shared__ float qs[64][68];      // 64 tokens x 64, padded

    // stage kv[b,h]
    {
        const float4* src = (const float4*)(kv + (size_t)(b * HEADS + h) * DKH * DKH);
        float4* dst = (float4*)kvs;
        #pragma unroll
        for (int i = 0; i < 4; i++) dst[i * 256 + tid] = src[i * 256 + tid];
    }
    // stage 64 q rows
    const int t0 = b * SEQ + st * 64;
    {
        const int rr = tid >> 4;
        const int cc = (tid & 15) * 4;
        #pragma unroll
        for (int i = 0; i < 4; i++) {
            int r = i * 16 + rr;
            *(float4*)&qs[r][cc] =
                *(const float4*)(qkv + (size_t)(t0 + r) * QKVN + h * DKH + cc);
        }
    }
    __syncthreads();

    const int tok = tid >> 2;   // 0..63
    const int tg  = tid & 3;    // e-range tg*16 .. tg*16+15
    float4 acc[4];
    #pragma unroll
    for (int i = 0; i < 4; i++) acc[i] = make_float4(0.f, 0.f, 0.f, 0.f);

    #pragma unroll 4
    for (int d = 0; d < DKH; d++) {
        float qd = qs[tok][d];
        #pragma unroll
        for (int i = 0; i < 4; i++) {
            float4 kk = *(const float4*)&kvs[d][tg * 16 + i * 4];
            acc[i].x += qd * kk.x; acc[i].y += qd * kk.y;
            acc[i].z += qd * kk.z; acc[i].w += qd * kk.w;
        }
    }

    float* o = attn + (size_t)(t0 + tok) * DMODEL + h * DKH + tg * 16;
    #pragma unroll
    for (int i = 0; i < 4; i++) {
        float4 v = acc[i];
        v.x = tf32_rna(v.x); v.y = tf32_rna(v.y);
        v.z = tf32_rna(v.z); v.w = tf32_rna(v.w);
        *(float4*)(o + i * 4) = v;
    }
}

// -------------------------------------------------------------------- launch --
extern "C" void kernel_launch(void* const* d_in, const int* in_sizes, int n_in,
                              void* d_out, int out_size) {
    (void)in_sizes; (void)n_in; (void)out_size;
    const float* x  = (const float*)d_in[0];
    const float* Wq = (const float*)d_in[1];
    const float* Wk = (const float*)d_in[2];
    const float* Wv = (const float*)d_in[3];
    const float* Wo = (const float*)d_in[4];
    float* out = (float*)d_out;

    float *xt, *wqkv, *wo, *qkv, *kvp, *kv, *attn;
    cudaGetSymbolAddress((void**)&xt,   g_xt);
    cudaGetSymbolAddress((void**)&wqkv, g_wqkv);
    cudaGetSymbolAddress((void**)&wo,   g_wo);
    cudaGetSymbolAddress((void**)&qkv,  g_qkv);
    cudaGetSymbolAddress((void**)&kvp,  g_kvp);
    cudaGetSymbolAddress((void**)&kv,   g_kv);
    cudaGetSymbolAddress((void**)&attn, g_attn);

    // 1) round inputs to tf32 (rna) once per call
    round_tf32_kernel<<<1024, 256>>>(x,  xt, NTOK * DMODEL / 4);
    round_tf32_kernel<<<256,  256>>>(Wq, wqkv,                       DMODEL * DMODEL / 4);
    round_tf32_kernel<<<256,  256>>>(Wk, wqkv +     DMODEL * DMODEL, DMODEL * DMODEL / 4);
    round_tf32_kernel<<<256,  256>>>(Wv, wqkv + 2 * DMODEL * DMODEL, DMODEL * DMODEL / 4);
    round_tf32_kernel<<<256,  256>>>(Wo, wo, DMODEL * DMODEL / 4);

    // 2) fused q|k|v projection
    gemm_tf32<<<dim3(QKVN / 128, NTOK / 128), 256>>>(xt, wqkv, qkv, DMODEL, QKVN);

    // 3) kv = K^T V per (b,h), split-S + deterministic reduce (scale folded)
    kv_partial_kernel<<<dim3(NSPLIT, HEADS, BATCH), 256>>>(qkv, kvp);
    kv_reduce_kernel<<<(BATCH * HEADS * DKH * DKH) / 256, 256>>>(kvp, kv);

    // 4) attn = q @ kv (fp32), rounded to tf32 for the output GEMM
    attn_kernel<<<dim3(SEQ / 64, HEADS, BATCH), 256>>>(qkv, kv, attn);

    // 5) out = attn @ Wo^T
    gemm_tf32<<<dim3(DMODEL / 128, NTOK / 128), 256>>>(attn, wo, out, DMODEL, DMODEL);
}

// round 6
// speedup vs baseline: 1.9411x; 1.9411x over previous
#include <cuda_runtime.h>
#include <cuda_fp16.h>
#include <cstdint>

// ----------------------------------------------------------------------------
// LinearMultiHeadAttention, fp16 mma.sync (legacy path — tcgen05 unavailable in
// this build: ptxas targets sm_103 base).
//   1) x, Wq|Wk|Wv  -> fp16 (rn)
//   2) qkv = x @ Wcat^T            (mma m16n8k16 f16, fp32 accum) -> fp16
//   3) kv[b,h] = scale * K^T V     (fp32 FFMA, split-S + deterministic reduce)
//   4) Zt[b][n][h*64+d] = sum_e Wo[n][h*64+e] * kv[b,h,d,e]   (fp32) -> fp16
//   5) out_b = q_b @ Zt_b^T        (mma f16, fp32 accum) -> fp32
// ----------------------------------------------------------------------------

static constexpr int BATCH  = 4;
static constexpr int SEQ    = 4096;
static constexpr int DMODEL = 1024;
static constexpr int HEADS  = 16;
static constexpr int DKH    = 64;
static constexpr int NTOK   = BATCH * SEQ;   // 16384
static constexpr int QKVN   = 3 * DMODEL;    // 3072
static constexpr int NSPLIT = 8;
static constexpr int SCHUNK = SEQ / NSPLIT;  // 512

// Scratch (__device__ globals; no allocations allowed)
__device__ __half g_xt[NTOK * DMODEL];                         // 32 MB
__device__ __half g_w[QKVN * DMODEL];                          // 6 MB
__device__ __half g_qkv[(size_t)NTOK * QKVN];                  // 96 MB
__device__ float  g_kvp[NSPLIT * BATCH * HEADS * DKH * DKH];   // 8 MB
__device__ float  g_kv[BATCH * HEADS * DKH * DKH];             // 1 MB
__device__ __half g_zt[BATCH * DMODEL * DMODEL];               // 8 MB

// ------------------------------------------------------------------ helpers --
__device__ __forceinline__ void cp16(uint32_t smem_dst, const void* gmem_src) {
    asm volatile("cp.async.cg.shared.global [%0], [%1], 16;"
                 :: "r"(smem_dst), "l"(gmem_src) : "memory");
}
__device__ __forceinline__ uint32_t smem_u32(const void* p) {
    uint32_t a;
    asm("{ .reg .u64 t; cvta.to.shared.u64 t, %1; cvt.u32.u64 %0, t; }"
        : "=r"(a) : "l"(p));
    return a;
}
__device__ __forceinline__ void store_pair(float* C, float a, float b) {
    *(float2*)C = make_float2(a, b);
}
__device__ __forceinline__ void store_pair(__half* C, float a, float b) {
    *(__half2*)C = __floats2half2_rn(a, b);
}

// ---------------------------------------------------------- fp32 -> fp16 ----
__global__ void f32_to_f16_kernel(const float* __restrict__ s,
                                  __half* __restrict__ d, int n4) {
    int i = blockIdx.x * blockDim.x + threadIdx.x;
    int stride = gridDim.x * blockDim.x;
    for (; i < n4; i += stride) {
        float4 v = ((const float4*)s)[i];
        __half2* o = (__half2*)d + 2 * (size_t)i;
        o[0] = __floats2half2_rn(v.x, v.y);
        o[1] = __floats2half2_rn(v.z, v.w);
    }
}

// ----------------------------------------------------------- fp16 GEMM ------
// C[M,N] = A[M,K] @ B[N,K]^T, fp16 in / fp32 accum / OutT out. K = 1024.
// CTA tile 128x128, warp tile 64x32 (2x4 warps), K-tile 32 (2 x k16 steps).
// cp.async double-buffered smem, rows padded to 40 halves (LDS conflict-free).

static constexpr int SRS = 40;   // smem row stride in halves (80 B)
static constexpr int GK  = 1024;
static constexpr int NKT = GK / 32;   // 32

template <typename OutT>
__global__ __launch_bounds__(256, 2)
void gemm_f16(const __half* __restrict__ A, const __half* __restrict__ B,
              OutT* __restrict__ C, int lda, int ldb, int ldc,
              size_t abatch, size_t bbatch, size_t cbatch) {
    __shared__ __half sm[2][2][128 * SRS];   // [stage][A/B][tile] = 40960 B

    const int tid  = threadIdx.x;
    const int lane = tid & 31;
    const int warp = tid >> 5;
    const int wm   = (warp >> 2) * 64;
    const int wn   = (warp & 3) * 32;
    const int m0   = blockIdx.y * 128;
    const int n0   = blockIdx.x * 128;
    const int zz   = blockIdx.z;

    const __half* Ab = A + zz * abatch + (size_t)m0 * lda;
    const __half* Bb = B + zz * bbatch + (size_t)n0 * ldb;
    OutT*         Cb = C + zz * cbatch;

    // fill mapping: idx -> (row = idx>>2, chunk = idx&3), chunk = 16 B = 8 halves
    auto prefetch = [&](int kt, int stage) {
        const uint32_t a_s = smem_u32(&sm[stage][0][0]);
        const uint32_t b_s = smem_u32(&sm[stage][1][0]);
        #pragma unroll
        for (int i = 0; i < 2; i++) {
            int idx = tid + i * 256;
            int row = idx >> 2, c = idx & 3;
            uint32_t off = (uint32_t)(row * (SRS * 2) + c * 16);
            cp16(a_s + off, Ab + (size_t)row * lda + kt * 32 + c * 8);
            cp16(b_s + off, Bb + (size_t)row * ldb + kt * 32 + c * 8);
        }
        asm volatile("cp.async.commit_group;" ::: "memory");
    };

    prefetch(0, 0);
    prefetch(1, 1);

    float c[4][4][4];
    #pragma unroll
    for (int i = 0; i < 4; i++)
        #pragma unroll
        for (int j = 0; j < 4; j++)
            #pragma unroll
            for (int k = 0; k < 4; k++) c[i][j][k] = 0.f;

    const int arow = wm + (lane >> 2);
    const int brow = wn + (lane >> 2);
    const int kc2  = (lane & 3) * 2;

    for (int kt = 0; kt < NKT; kt++) {
        if (kt + 1 < NKT) asm volatile("cp.async.wait_group 1;" ::: "memory");
        else              asm volatile("cp.async.wait_group 0;" ::: "memory");
        __syncthreads();

        const __half* As = &sm[kt & 1][0][0];
        const __half* Bs = &sm[kt & 1][1][0];

        #pragma unroll
        for (int ks = 0; ks < 2; ks++) {
            uint32_t a[4][4], b[4][2];
            #pragma unroll
            for (int fm = 0; fm < 4; fm++) {
                const __half* p = As + (arow + fm * 16) * SRS + ks * 16 + kc2;
                a[fm][0] = *(const uint32_t*)p;
                a[fm][1] = *(const uint32_t*)(p + 8 * SRS);
                a[fm][2] = *(const uint32_t*)(p + 8);
                a[fm][3] = *(const uint32_t*)(p + 8 * SRS + 8);
            }
            #pragma unroll
            for (int fn = 0; fn < 4; fn++) {
                const __half* p = Bs + (brow + fn * 8) * SRS + ks * 16 + kc2;
                b[fn][0] = *(const uint32_t*)p;
                b[fn][1] = *(const uint32_t*)(p + 8);
            }
            #pragma unroll
            for (int fm = 0; fm < 4; fm++)
                #pragma unroll
                for (int fn = 0; fn < 4; fn++)
                    asm volatile(
                        "mma.sync.aligned.m16n8k16.row.col.f32.f16.f16.f32 "
                        "{%0,%1,%2,%3},{%4,%5,%6,%7},{%8,%9},{%0,%1,%2,%3};"
                        : "+f"(c[fm][fn][0]), "+f"(c[fm][fn][1]),
                          "+f"(c[fm][fn][2]), "+f"(c[fm][fn][3])
                        : "r"(a[fm][0]), "r"(a[fm][1]),
                          "r"(a[fm][2]), "r"(a[fm][3]),
                          "r"(b[fn][0]), "r"(b[fn][1]));
        }
        __syncthreads();
        if (kt + 2 < NKT) prefetch(kt + 2, kt & 1);
    }

    #pragma unroll
    for (int fm = 0; fm < 4; fm++) {
        int r = m0 + wm + fm * 16 + (lane >> 2);
        #pragma unroll
        for (int fn = 0; fn < 4; fn++) {
            int cc = n0 + wn + fn * 8 + (lane & 3) * 2;
            store_pair(Cb + (size_t)r * ldc + cc,       c[fm][fn][0], c[fm][fn][1]);
            store_pair(Cb + (size_t)(r + 8) * ldc + cc, c[fm][fn][2], c[fm][fn][3]);
        }
    }
}

// ------------------------------------------------------------- kv partials --
// kv_partial[sp,b,h,d,e] = sum_{s in chunk} k[b,s,h,d] * v[b,s,h,e]  (fp32)
__global__ void kv_partial_kernel(const __half* __restrict__ qkv,
                                  float* __restrict__ kvp) {
    const int sp = blockIdx.x, h = blockIdx.y, b = blockIdx.z;
    const int tid = threadIdx.x;
    __shared__ float ks[16][64];
    __shared__ float vs[16][64];

    const int td = (tid >> 4) * 4;
    const int te = (tid & 15) * 4;
    const int ss = tid >> 4;
    const int dd = (tid & 15) * 4;

    float acc[4][4];
    #pragma unroll
    for (int i = 0; i < 4; i++)
        #pragma unroll
        for (int j = 0; j < 4; j++) acc[i][j] = 0.f;

    const int t0 = b * SEQ + sp * SCHUNK;
    for (int s = 0; s < SCHUNK; s += 16) {
        const __half* base = qkv + (size_t)(t0 + s + ss) * QKVN + h * DKH;
        __half2 k01 = *(const __half2*)(base + DMODEL + dd);
        __half2 k23 = *(const __half2*)(base + DMODEL + dd + 2);
        __half2 v01 = *(const __half2*)(base + 2 * DMODEL + dd);
        __half2 v23 = *(const __half2*)(base + 2 * DMODEL + dd + 2);
        float2 kf01 = __half22float2(k01), kf23 = __half22float2(k23);
        float2 vf01 = __half22float2(v01), vf23 = __half22float2(v23);
        *(float4*)&ks[ss][dd] = make_float4(kf01.x, kf01.y, kf23.x, kf23.y);
        *(float4*)&vs[ss][dd] = make_float4(vf01.x, vf01.y, vf23.x, vf23.y);
        __syncthreads();
        #pragma unroll
        for (int j = 0; j < 16; j++) {
            float4 kk = *(const float4*)&ks[j][td];
            float4 vv = *(const float4*)&vs[j][te];
            float ka[4] = {kk.x, kk.y, kk.z, kk.w};
            #pragma unroll
            for (int i = 0; i < 4; i++) {
                acc[i][0] += ka[i] * vv.x;
                acc[i][1] += ka[i] * vv.y;
                acc[i][2] += ka[i] * vv.z;
                acc[i][3] += ka[i] * vv.w;
            }
        }
        __syncthreads();
    }

    float* o = kvp + (size_t)(((sp * BATCH + b) * HEADS + h) * DKH) * DKH;
    #pragma unroll
    for (int i = 0; i < 4; i++)
        *(float4*)(o + (td + i) * DKH + te) =
            make_float4(acc[i][0], acc[i][1], acc[i][2], acc[i][3]);
}

// kv[b,h,d,e] = scale * sum_sp kvp[...]   (deterministic)
__global__ void kv_reduce_kernel(const float* __restrict__ kvp,
                                 float* __restrict__ kv) {
    int idx = blockIdx.x * blockDim.x + threadIdx.x;
    float s = 0.f;
    #pragma unroll
    for (int sp = 0; sp < NSPLIT; sp++)
        s += kvp[(size_t)sp * (BATCH * HEADS * DKH * DKH) + idx];
    kv[idx] = s * 0.125f;   // 1/sqrt(64)
}

// -------------------------------------------------------------- Z build -----
// Zt[b][n][h*64+d] = sum_e Wo[n][h*64+e] * kv[b,h,d,e]   (fp32 -> fp16)
__global__ void zbuild_kernel(const float* __restrict__ kv,
                              const float* __restrict__ Wo,
                              __half* __restrict__ zt) {
    const int nb = blockIdx.x, h = blockIdx.y, b = blockIdx.z;
    const int tid = threadIdx.x;
    __shared__ float wos[64][64];   // [n][e]
    __shared__ float kvs[64][64];   // [d][e]

    {
        const int r = tid >> 2;
        const int c0 = (tid & 3) * 16;
        const float* wsrc = Wo + (size_t)(nb * 64 + r) * DMODEL + h * DKH;
        const float* ksrc = kv + (size_t)((b * HEADS + h) * DKH + r) * DKH;
        #pragma unroll
        for (int i = 0; i < 4; i++) {
            *(float4*)&wos[r][c0 + i * 4] = *(const float4*)(wsrc + c0 + i * 4);
            *(float4*)&kvs[r][c0 + i * 4] = *(const float4*)(ksrc + c0 + i * 4);
        }
    }
    __syncthreads();

    const int tn = (tid >> 4) * 4;
    const int td = (tid & 15) * 4;
    float acc[4][4];
    #pragma unroll
    for (int i = 0; i < 4; i++)
        #pragma unroll
        for (int j = 0; j < 4; j++) acc[i][j] = 0.f;

    for (int e = 0; e < 64; e += 4) {
        float4 w[4], k[4];
        #pragma unroll
        for (int i = 0; i < 4; i++) w[i] = *(const float4*)&wos[tn + i][e];
        #pragma unroll
        for (int j = 0; j < 4; j++) k[j] = *(const float4*)&kvs[td + j][e];
        #pragma unroll
        for (int i = 0; i < 4; i++)
            #pragma unroll
            for (int j = 0; j < 4; j++)
                acc[i][j] += w[i].x * k[j].x + w[i].y * k[j].y +
                             w[i].z * k[j].z + w[i].w * k[j].w;
    }

    #pragma unroll
    for (int i = 0; i < 4; i++) {
        __half* o = zt + (size_t)(b * DMODEL + nb * 64 + tn + i) * DMODEL
                       + h * DKH + td;
        ((__half2*)o)[0] = __floats2half2_rn(acc[i][0], acc[i][1]);
        ((__half2*)o)[1] = __floats2half2_rn(acc[i][2], acc[i][3]);
    }
}

// -------------------------------------------------------------------- launch --
extern "C" void kernel_launch(void* const* d_in, const int* in_sizes, int n_in,
                              void* d_out, int out_size) {
    (void)in_sizes; (void)n_in; (void)out_size;
    const float* x  = (const float*)d_in[0];
    const float* Wq = (const float*)d_in[1];
    const float* Wk = (const float*)d_in[2];
    const float* Wv = (const float*)d_in[3];
    const float* Wo = (const float*)d_in[4];
    float* out = (float*)d_out;

    __half *xt, *w, *qkv, *zt;
    float *kvp, *kv;
    cudaGetSymbolAddress((void**)&xt,  g_xt);
    cudaGetSymbolAddress((void**)&w,   g_w);
    cudaGetSymbolAddress((void**)&qkv, g_qkv);
    cudaGetSymbolAddress((void**)&kvp, g_kvp);
    cudaGetSymbolAddress((void**)&kv,  g_kv);
    cudaGetSymbolAddress((void**)&zt,  g_zt);

    // 1) convert to fp16
    f32_to_f16_kernel<<<1024, 256>>>(x,  xt, NTOK * DMODEL / 4);
    f32_to_f16_kernel<<<256,  256>>>(Wq, w,                       DMODEL * DMODEL / 4);
    f32_to_f16_kernel<<<256,  256>>>(Wk, w +     DMODEL * DMODEL, DMODEL * DMODEL / 4);
    f32_to_f16_kernel<<<256,  256>>>(Wv, w + 2 * DMODEL * DMODEL, DMODEL * DMODEL / 4);

    // 2) qkv = x @ Wcat^T  -> fp16 [16384, 3072]
    gemm_f16<__half><<<dim3(QKVN / 128, NTOK / 128, 1), 256>>>(
        xt, w, qkv, DMODEL, DMODEL, QKVN, 0, 0, 0);

    // 3) kv = scale * K^T V  per (b,h)
    kv_partial_kernel<<<dim3(NSPLIT, HEADS, BATCH), 256>>>(qkv, kvp);
    kv_reduce_kernel<<<(BATCH * HEADS * DKH * DKH) / 256, 256>>>(kvp, kv);

    // 4) Zt[b] = (kv @ Wo^T) transposed into [n][hd], fp16
    zbuild_kernel<<<dim3(DMODEL / 64, HEADS, BATCH), 256>>>(kv, Wo, zt);

    // 5) out_b = q_b @ Zt_b^T  (A = q slice of qkv, lda = 3072)
    gemm_f16<float><<<dim3(DMODEL / 128, SEQ / 128, BATCH), 256>>>(
        qkv, zt, out, QKVN, DMODEL, DMODEL,
        (size_t)SEQ * QKVN, (size_t)DMODEL * DMODEL, (size_t)SEQ * DMODEL);
}

// round 7
// speedup vs baseline: 2.3651x; 1.2184x over previous
#include <cuda_runtime.h>
#include <cuda_fp16.h>
#include <cstdint>

// ----------------------------------------------------------------------------
// LinearMultiHeadAttention, fully reassociated (fp16 mma.sync, fp32 accum):
//   G_b  = x_b^T x_b                      (fp16 GEMM, M=N=1024, K=4096)
//   T1_b = Wk @ G_b                       (fp16 GEMM, M=N=K=1024)
//   kv[b,h] = 0.125 * T1_h @ Wv_h^T       (fp32 FFMA block-diag, 64x64 per head)
//   Zt_b[n][hd] = sum_e Wo[n][he] kv[b,h,d,e]      (fp32)
//   Pt_b = Zt_b @ Wq_t^T                  (fp16 GEMM, M=N=K=1024)
//   out_b = x_b @ Pt_b^T                  (fp16 GEMM, M=4096, N=K=1024, fp32 out)
// Total ~86 GF vs 137 GF for the direct qkv formulation; qkv scratch eliminated.
// ----------------------------------------------------------------------------

static constexpr int BATCH  = 4;
static constexpr int SEQ    = 4096;
static constexpr int DMODEL = 1024;
static constexpr int HEADS  = 16;
static constexpr int DKH    = 64;
static constexpr int NTOK   = BATCH * SEQ;   // 16384

// Scratch (__device__ globals; no allocations allowed)
__device__ __half g_xt[NTOK * DMODEL];                 // 32 MB  x fp16 [b][t][c]
__device__ __half g_xT[NTOK * DMODEL];                 // 32 MB  x fp16 [b][c][t]
__device__ __half g_wk[DMODEL * DMODEL];               // 2 MB
__device__ __half g_wv[DMODEL * DMODEL];               // 2 MB
__device__ __half g_wqt[DMODEL * DMODEL];              // 2 MB   Wq^T [c][hd]
__device__ __half g_G[BATCH * DMODEL * DMODEL];        // 8 MB
__device__ __half g_t1[BATCH * DMODEL * DMODEL];       // 8 MB
__device__ float  g_kv[BATCH * HEADS * DKH * DKH];     // 1 MB
__device__ __half g_zt[BATCH * DMODEL * DMODEL];       // 8 MB
__device__ __half g_pt[BATCH * DMODEL * DMODEL];       // 8 MB

// ------------------------------------------------------------------ helpers --
__device__ __forceinline__ void cp16(uint32_t smem_dst, const void* gmem_src) {
    asm volatile("cp.async.cg.shared.global [%0], [%1], 16;"
                 :: "r"(smem_dst), "l"(gmem_src) : "memory");
}
__device__ __forceinline__ uint32_t smem_u32(const void* p) {
    uint32_t a;
    asm("{ .reg .u64 t; cvta.to.shared.u64 t, %1; cvt.u32.u64 %0, t; }"
        : "=r"(a) : "l"(p));
    return a;
}
__device__ __forceinline__ void store_pair(float* C, float a, float b) {
    *(float2*)C = make_float2(a, b);
}
__device__ __forceinline__ void store_pair(__half* C, float a, float b) {
    *(__half2*)C = __floats2half2_rn(a, b);
}

// --------------------------------------------------------------- converts ---
__global__ void f32_to_f16_kernel(const float* __restrict__ s,
                                  __half* __restrict__ d, int n4) {
    int i = blockIdx.x * blockDim.x + threadIdx.x;
    int stride = gridDim.x * blockDim.x;
    for (; i < n4; i += stride) {
        float4 v = ((const float4*)s)[i];
        __half2* o = (__half2*)d + 2 * (size_t)i;
        o[0] = __floats2half2_rn(v.x, v.y);
        o[1] = __floats2half2_rn(v.z, v.w);
    }
}

// x fp32 [b][t][c] -> xt fp16 [b][t][c] AND xT fp16 [b][c][t]
__global__ void convert_transpose_x(const float* __restrict__ x,
                                    __half* __restrict__ xt,
                                    __half* __restrict__ xT) {
    __shared__ __half tile[32][33];
    const int c0 = blockIdx.x * 32;
    const int t0 = blockIdx.y * 32;                  // 4096 % 32 == 0: no straddle
    const int tx = threadIdx.x & 31;
    const int ty = threadIdx.x >> 5;                 // 0..7
    #pragma unroll
    for (int i = 0; i < 4; i++) {
        int t = t0 + ty + i * 8;
        __half h = __float2half_rn(x[(size_t)t * DMODEL + c0 + tx]);
        xt[(size_t)t * DMODEL + c0 + tx] = h;
        tile[ty + i * 8][tx] = h;
    }
    __syncthreads();
    const int b = t0 >> 12;
    const int tl = t0 & 4095;
    #pragma unroll
    for (int i = 0; i < 4; i++) {
        int c = c0 + ty + i * 8;
        xT[((size_t)b * DMODEL + c) * SEQ + tl + tx] = tile[tx][ty + i * 8];
    }
}

// W fp32 [r][c] (1024x1024) -> Wt fp16 [c][r]
__global__ void convert_transpose_w(const float* __restrict__ W,
                                    __half* __restrict__ Wt) {
    __shared__ __half tile[32][33];
    const int c0 = blockIdx.x * 32;
    const int r0 = blockIdx.y * 32;
    const int tx = threadIdx.x & 31;
    const int ty = threadIdx.x >> 5;
    #pragma unroll
    for (int i = 0; i < 4; i++) {
        int r = r0 + ty + i * 8;
        tile[ty + i * 8][tx] = __float2half_rn(W[(size_t)r * DMODEL + c0 + tx]);
    }
    __syncthreads();
    #pragma unroll
    for (int i = 0; i < 4; i++) {
        int c = c0 + ty + i * 8;
        Wt[(size_t)c * DMODEL + r0 + tx] = tile[tx][ty + i * 8];
    }
}

// ----------------------------------------------------------- fp16 GEMM ------
// C[M,N] = A[M,K] @ B[N,K]^T, fp16 in / fp32 accum / OutT out. Runtime K.
// CTA tile 128x128, warp tile 64x32 (2x4 warps), K-tile 32 (2 x k16 steps).

static constexpr int SRS = 40;   // smem row stride in halves (80 B)

template <typename OutT>
__global__ __launch_bounds__(256, 2)
void gemm_f16(const __half* __restrict__ A, const __half* __restrict__ B,
              OutT* __restrict__ C, int lda, int ldb, int ldc, int nkt,
              size_t abatch, size_t bbatch, size_t cbatch) {
    __shared__ __half sm[2][2][128 * SRS];   // 40960 B

    const int tid  = threadIdx.x;
    const int lane = tid & 31;
    const int warp = tid >> 5;
    const int wm   = (warp >> 2) * 64;
    const int wn   = (warp & 3) * 32;
    const int m0   = blockIdx.y * 128;
    const int n0   = blockIdx.x * 128;
    const int zz   = blockIdx.z;

    const __half* Ab = A + zz * abatch + (size_t)m0 * lda;
    const __half* Bb = B + zz * bbatch + (size_t)n0 * ldb;
    OutT*         Cb = C + zz * cbatch;

    auto prefetch = [&](int kt, int stage) {
        const uint32_t a_s = smem_u32(&sm[stage][0][0]);
        const uint32_t b_s = smem_u32(&sm[stage][1][0]);
        #pragma unroll
        for (int i = 0; i < 2; i++) {
            int idx = tid + i * 256;
            int row = idx >> 2, c = idx & 3;
            uint32_t off = (uint32_t)(row * (SRS * 2) + c * 16);
            cp16(a_s + off, Ab + (size_t)row * lda + kt * 32 + c * 8);
            cp16(b_s + off, Bb + (size_t)row * ldb + kt * 32 + c * 8);
        }
        asm volatile("cp.async.commit_group;" ::: "memory");
    };

    prefetch(0, 0);
    prefetch(1, 1);

    float c[4][4][4];
    #pragma unroll
    for (int i = 0; i < 4; i++)
        #pragma unroll
        for (int j = 0; j < 4; j++)
            #pragma unroll
            for (int k = 0; k < 4; k++) c[i][j][k] = 0.f;

    const int arow = wm + (lane >> 2);
    const int brow = wn + (lane >> 2);
    const int kc2  = (lane & 3) * 2;

    for (int kt = 0; kt < nkt; kt++) {
        if (kt + 1 < nkt) asm volatile("cp.async.wait_group 1;" ::: "memory");
        else              asm volatile("cp.async.wait_group 0;" ::: "memory");
        __syncthreads();

        const __half* As = &sm[kt & 1][0][0];
        const __half* Bs = &sm[kt & 1][1][0];

        #pragma unroll
        for (int ks = 0; ks < 2; ks++) {
            uint32_t a[4][4], b[4][2];
            #pragma unroll
            for (int fm = 0; fm < 4; fm++) {
                const __half* p = As + (arow + fm * 16) * SRS + ks * 16 + kc2;
                a[fm][0] = *(const uint32_t*)p;
                a[fm][1] = *(const uint32_t*)(p + 8 * SRS);
                a[fm][2] = *(const uint32_t*)(p + 8);
                a[fm][3] = *(const uint32_t*)(p + 8 * SRS + 8);
            }
            #pragma unroll
            for (int fn = 0; fn < 4; fn++) {
                const __half* p = Bs + (brow + fn * 8) * SRS + ks * 16 + kc2;
                b[fn][0] = *(const uint32_t*)p;
                b[fn][1] = *(const uint32_t*)(p + 8);
            }
            #pragma unroll
            for (int fm = 0; fm < 4; fm++)
                #pragma unroll
                for (int fn = 0; fn < 4; fn++)
                    asm volatile(
                        "mma.sync.aligned.m16n8k16.row.col.f32.f16.f16.f32 "
                        "{%0,%1,%2,%3},{%4,%5,%6,%7},{%8,%9},{%0,%1,%2,%3};"
                        : "+f"(c[fm][fn][0]), "+f"(c[fm][fn][1]),
                          "+f"(c[fm][fn][2]), "+f"(c[fm][fn][3])
                        : "r"(a[fm][0]), "r"(a[fm][1]),
                          "r"(a[fm][2]), "r"(a[fm][3]),
                          "r"(b[fn][0]), "r"(b[fn][1]));
        }
        __syncthreads();
        if (kt + 2 < nkt) prefetch(kt + 2, kt & 1);
    }

    #pragma unroll
    for (int fm = 0; fm < 4; fm++) {
        int r = m0 + wm + fm * 16 + (lane >> 2);
        #pragma unroll
        for (int fn = 0; fn < 4; fn++) {
            int cc = n0 + wn + fn * 8 + (lane & 3) * 2;
            store_pair(Cb + (size_t)r * ldc + cc,       c[fm][fn][0], c[fm][fn][1]);
            store_pair(Cb + (size_t)(r + 8) * ldc + cc, c[fm][fn][2], c[fm][fn][3]);
        }
    }
}

// ----------------------------------------------------- kv from T1 (tiny) ----
// kv[b,h,d,e] = 0.125 * sum_c T1[b][h*64+d][c] * Wv[h*64+e][c]
__global__ void kv_from_t1(const __half* __restrict__ T1,
                           const __half* __restrict__ Wv,
                           float* __restrict__ kv) {
    const int h = blockIdx.x, b = blockIdx.y;
    const int tid = threadIdx.x;
    __shared__ float t1s[64][36];
    __shared__ float wvs[64][36];

    const int row = tid >> 2;
    const int seg = (tid & 3) * 8;
    const int td  = (tid >> 4) * 4;
    const int te  = (tid & 15) * 4;

    const __half* t1b = T1 + ((size_t)b * DMODEL + h * DKH) * DMODEL;
    const __half* wvb = Wv + (size_t)(h * DKH) * DMODEL;

    float acc[4][4];
    #pragma unroll
    for (int i = 0; i < 4; i++)
        #pragma unroll
        for (int j = 0; j < 4; j++) acc[i][j] = 0.f;

    for (int c0 = 0; c0 < DMODEL; c0 += 32) {
        #pragma unroll
        for (int u = 0; u < 4; u++) {
            float2 f = __half22float2(
                *(const __half2*)(t1b + (size_t)row * DMODEL + c0 + seg + 2 * u));
            t1s[row][seg + 2 * u]     = f.x;
            t1s[row][seg + 2 * u + 1] = f.y;
            float2 g = __half22float2(
                *(const __half2*)(wvb + (size_t)row * DMODEL + c0 + seg + 2 * u));
            wvs[row][seg + 2 * u]     = g.x;
            wvs[row][seg + 2 * u + 1] = g.y;
        }
        __syncthreads();
        #pragma unroll
        for (int kk = 0; kk < 32; kk++) {
            float a0 = t1s[td + 0][kk], a1 = t1s[td + 1][kk];
            float a2 = t1s[td + 2][kk], a3 = t1s[td + 3][kk];
            float b0 = wvs[te + 0][kk], b1 = wvs[te + 1][kk];
            float b2 = wvs[te + 2][kk], b3 = wvs[te + 3][kk];
            acc[0][0] += a0 * b0; acc[0][1] += a0 * b1;
            acc[0][2] += a0 * b2; acc[0][3] += a0 * b3;
            acc[1][0] += a1 * b0; acc[1][1] += a1 * b1;
            acc[1][2] += a1 * b2; acc[1][3] += a1 * b3;
            acc[2][0] += a2 * b0; acc[2][1] += a2 * b1;
            acc[2][2] += a2 * b2; acc[2][3] += a2 * b3;
            acc[3][0] += a3 * b0; acc[3][1] += a3 * b1;
            acc[3][2] += a3 * b2; acc[3][3] += a3 * b3;
        }
        __syncthreads();
    }

    float* o = kv + (size_t)((b * HEADS + h) * DKH) * DKH;
    #pragma unroll
    for (int i = 0; i < 4; i++)
        #pragma unroll
        for (int j = 0; j < 4; j++)
            o[(size_t)(td + i) * DKH + te + j] = acc[i][j] * 0.125f;
}

// -------------------------------------------------------------- Z build -----
// Zt[b][n][h*64+d] = sum_e Wo[n][h*64+e] * kv[b,h,d,e]   (fp32 -> fp16)
__global__ void zbuild_kernel(const float* __restrict__ kv,
                              const float* __restrict__ Wo,
                              __half* __restrict__ zt) {
    const int nb = blockIdx.x, h = blockIdx.y, b = blockIdx.z;
    const int tid = threadIdx.x;
    __shared__ float wos[64][64];
    __shared__ float kvs[64][64];

    {
        const int r = tid >> 2;
        const int c0 = (tid & 3) * 16;
        const float* wsrc = Wo + (size_t)(nb * 64 + r) * DMODEL + h * DKH;
        const float* ksrc = kv + (size_t)((b * HEADS + h) * DKH + r) * DKH;
        #pragma unroll
        for (int i = 0; i < 4; i++) {
            *(float4*)&wos[r][c0 + i * 4] = *(const float4*)(wsrc + c0 + i * 4);
            *(float4*)&kvs[r][c0 + i * 4] = *(const float4*)(ksrc + c0 + i * 4);
        }
    }
    __syncthreads();

    const int tn = (tid >> 4) * 4;
    const int td = (tid & 15) * 4;
    float acc[4][4];
    #pragma unroll
    for (int i = 0; i < 4; i++)
        #pragma unroll
        for (int j = 0; j < 4; j++) acc[i][j] = 0.f;

    for (int e = 0; e < 64; e += 4) {
        float4 w[4], k[4];
        #pragma unroll
        for (int i = 0; i < 4; i++) w[i] = *(const float4*)&wos[tn + i][e];
        #pragma unroll
        for (int j = 0; j < 4; j++) k[j] = *(const float4*)&kvs[td + j][e];
        #pragma unroll
        for (int i = 0; i < 4; i++)
            #pragma unroll
            for (int j = 0; j < 4; j++)
                acc[i][j] += w[i].x * k[j].x + w[i].y * k[j].y +
                             w[i].z * k[j].z + w[i].w * k[j].w;
    }

    #pragma unroll
    for (int i = 0; i < 4; i++) {
        __half* o = zt + (size_t)(b * DMODEL + nb * 64 + tn + i) * DMODEL
                       + h * DKH + td;
        ((__half2*)o)[0] = __floats2half2_rn(acc[i][0], acc[i][1]);
        ((__half2*)o)[1] = __floats2half2_rn(acc[i][2], acc[i][3]);
    }
}

// -------------------------------------------------------------------- launch --
extern "C" void kernel_launch(void* const* d_in, const int* in_sizes, int n_in,
                              void* d_out, int out_size) {
    (void)in_sizes; (void)n_in; (void)out_size;
    const float* x  = (const float*)d_in[0];
    const float* Wq = (const float*)d_in[1];
    const float* Wk = (const float*)d_in[2];
    const float* Wv = (const float*)d_in[3];
    const float* Wo = (const float*)d_in[4];
    float* out = (float*)d_out;

    __half *xt, *xT, *wk, *wv, *wqt, *G, *t1, *zt, *pt;
    float *kv;
    cudaGetSymbolAddress((void**)&xt,  g_xt);
    cudaGetSymbolAddress((void**)&xT,  g_xT);
    cudaGetSymbolAddress((void**)&wk,  g_wk);
    cudaGetSymbolAddress((void**)&wv,  g_wv);
    cudaGetSymbolAddress((void**)&wqt, g_wqt);
    cudaGetSymbolAddress((void**)&G,   g_G);
    cudaGetSymbolAddress((void**)&t1,  g_t1);
    cudaGetSymbolAddress((void**)&kv,  g_kv);
    cudaGetSymbolAddress((void**)&zt,  g_zt);
    cudaGetSymbolAddress((void**)&pt,  g_pt);

    const size_t DD = (size_t)DMODEL * DMODEL;

    // 1) converts: x -> xt + xT (fused transpose); Wk, Wv fp16; Wq -> Wq^T fp16
    convert_transpose_x<<<dim3(DMODEL / 32, NTOK / 32), 256>>>(x, xt, xT);
    f32_to_f16_kernel<<<256, 256>>>(Wk, wk, DMODEL * DMODEL / 4);
    f32_to_f16_kernel<<<256, 256>>>(Wv, wv, DMODEL * DMODEL / 4);
    convert_transpose_w<<<dim3(32, 32), 256>>>(Wq, wqt);

    // 2) G_b = x_b^T x_b  (A = B = xT_b, K = 4096)
    gemm_f16<__half><<<dim3(8, 8, BATCH), 256>>>(
        xT, xT, G, SEQ, SEQ, DMODEL, SEQ / 32,
        (size_t)DMODEL * SEQ, (size_t)DMODEL * SEQ, DD);

    // 3) T1_b = Wk @ G_b  (G symmetric -> row-major B works)
    gemm_f16<__half><<<dim3(8, 8, BATCH), 256>>>(
        wk, G, t1, DMODEL, DMODEL, DMODEL, DMODEL / 32, 0, DD, DD);

    // 4) kv[b,h] = 0.125 * T1_h @ Wv_h^T   (block-diagonal, fp32)
    kv_from_t1<<<dim3(HEADS, BATCH), 256>>>(t1, wv, kv);

    // 5) Zt_b = (kv @ Wo^T) laid out [n][hd], fp16
    zbuild_kernel<<<dim3(DMODEL / 64, HEADS, BATCH), 256>>>(kv, Wo, zt);

    // 6) Pt_b[n][c] = sum_hd Zt_b[n][hd] * Wq[hd][c]   (B = Wq^T)
    gemm_f16<__half><<<dim3(8, 8, BATCH), 256>>>(
        zt, wqt, pt, DMODEL, DMODEL, DMODEL, DMODEL / 32, DD, 0, DD);

    // 7) out_b = x_b @ Pt_b^T  -> fp32
    gemm_f16<float><<<dim3(8, SEQ / 128, BATCH), 256>>>(
        xt, pt, out, DMODEL, DMODEL, DMODEL, DMODEL / 32,
        (size_t)SEQ * DMODEL, DD, (size_t)SEQ * DMODEL);
}